// round 15
// baseline (speedup 1.0000x reference)
#include <cuda_runtime.h>
#include <cuda_bf16.h>

#define FULL_MASK 0xFFFFFFFFu
#define WPB 4          // warps per block (render)
#define NMAX 65536

// Segment start offsets: g_start[r] = first sample of ray r, g_start[N] = M.
__device__ int g_start[NMAX + 1];

__device__ __forceinline__ float tanh_fast(float x) {
    float y;
    asm("tanh.approx.f32 %0, %1;" : "=f"(y) : "f"(x));
    return y;
}
// sigmoid(x) = 0.5*tanh(0.5x) + 0.5  (single MUFU)
__device__ __forceinline__ float sigmoid_fast(float x) {
    return fmaf(tanh_fast(0.5f * x), 0.5f, 0.5f);
}

// ---------------------------------------------------------------------------
// Kernel 1: boundary detection over the sorted ray_id array (int4 per thread).
// Writes g_start[r] for every boundary (covers empty rays); the tail thread
// fills g_start[last+1 .. N] = M.
// ---------------------------------------------------------------------------
__global__ void __launch_bounds__(256)
boundary_kernel(const int* __restrict__ ray_id, int M, int N)
{
    const int t = blockIdx.x * blockDim.x + threadIdx.x;
    const int i = t * 4;
    if (i >= M) return;

    if (i + 4 <= M) {
        const int4 v = *(const int4*)(ray_id + i);
        const int a = (i == 0) ? -1 : __ldg(ray_id + i - 1);
        if (a   != v.x) for (int r = a   + 1; r <= v.x; r++) g_start[r] = i;
        if (v.x != v.y) for (int r = v.x + 1; r <= v.y; r++) g_start[r] = i + 1;
        if (v.y != v.z) for (int r = v.y + 1; r <= v.z; r++) g_start[r] = i + 2;
        if (v.z != v.w) for (int r = v.z + 1; r <= v.w; r++) g_start[r] = i + 3;
        if (i + 4 == M)
            for (int r = v.w + 1; r <= N; r++) g_start[r] = M;
    } else {
        int a = (i == 0) ? -1 : __ldg(ray_id + i - 1);
        for (int j = i; j < M; j++) {
            int b = __ldg(ray_id + j);
            if (a != b) for (int r = a + 1; r <= b; r++) g_start[r] = j;
            a = b;
        }
        for (int r = a + 1; r <= N; r++) g_start[r] = M;
    }
}

// ---------------------------------------------------------------------------
// Kernel 2: one warp per ray. Interleaved K=8 layout: within each 256-sample
// chunk, lane L owns samples [chunk + 8L, +8) as two aligned quads ->
// 8 unconditional float4 loads per lane, perfectly coalesced, all issued
// before the compute (MLP=8). Clamped bases (min(b, M-4)) keep loads
// in-bounds; clamped lanes are fully invalid and masked by the per-sample
// validity select. Colors fold into lane-local weighted sums before the
// single per-chunk warp product scan; `carry` links chunks (most rays: 1).
//
// Math (interval = 0.5):
//   t  = density*log2(e) + shift*log2(e)      (invalid sample -> t = -200)
//   ex = 2^t,  om = rsqrt(1+ex) = exp(-0.5*softplus(x)),  alpha = 1 - om
//   alphainv_last = final carry.
// ---------------------------------------------------------------------------
__global__ void __launch_bounds__(WPB * 32)
render_kernel(const float* __restrict__ density,
              const float* __restrict__ rgb_raw,
              const float* __restrict__ shift,
              float*       __restrict__ out,
              int M, int N)
{
    const int warp = blockIdx.x * WPB + (threadIdx.x >> 5);
    if (warp >= N) return;
    const int lane = threadIdx.x & 31;

    const float L2E = 1.4426950408889634f;
    const float shl = __ldg(shift) * L2E;

    const int start = g_start[warp];
    const int end   = g_start[warp + 1];
    const int a0    = start & ~3;               // 4-aligned loop base
    const unsigned len = (unsigned)(end - start);
    const int bmax  = M - 4;                    // highest legal float4 base

    float carry = 1.0f;
    float accR = 0.f, accG = 0.f, accB = 0.f;

    for (int itb = a0; itb < end; itb += 256) {
        const int b   = itb + 8 * lane;         // this lane's 8-sample base
        const int cb0 = min(b,     bmax);       // clamped quad bases
        const int cb1 = min(b + 4, bmax);

        const float4 dA = __ldcs((const float4*)(density + cb0));
        const float4 dB = __ldcs((const float4*)(density + cb1));
        const float4* rpA = (const float4*)(rgb_raw + 3 * cb0);
        const float4* rpB = (const float4*)(rgb_raw + 3 * cb1);
        const float4 rA0 = __ldcs(rpA + 0);
        const float4 rA1 = __ldcs(rpA + 1);
        const float4 rA2 = __ldcs(rpA + 2);
        const float4 rB0 = __ldcs(rpB + 0);
        const float4 rB1 = __ldcs(rpB + 1);
        const float4 rB2 = __ldcs(rpB + 2);

        const float dv[8]  = { dA.x, dA.y, dA.z, dA.w, dB.x, dB.y, dB.z, dB.w };
        const float cc[24] = { rA0.x, rA0.y, rA0.z, rA0.w, rA1.x, rA1.y,
                               rA1.z, rA1.w, rA2.x, rA2.y, rA2.z, rA2.w,
                               rB0.x, rB0.y, rB0.z, rB0.w, rB1.x, rB1.y,
                               rB1.z, rB1.w, rB2.x, rB2.y, rB2.z, rB2.w };

        float q = 1.0f;                         // lane-local product of om
        float vR = 0.f, vG = 0.f, vB = 0.f;
        #pragma unroll
        for (int j = 0; j < 8; ++j) {
            const bool valid = (unsigned)(b + j - start) < len;
            float t = fmaf(dv[j], L2E, shl);
            t = valid ? t : -200.0f;            // 2^-200 -> ex=0, om=1, alpha=0
            const float ex = exp2f(t);
            const float o  = rsqrtf(1.0f + ex); // om = exp(-s)
            const float w  = (1.0f - o) * q;    // alpha * lane-prefix
            vR = fmaf(w, sigmoid_fast(cc[3*j + 0]), vR);
            vG = fmaf(w, sigmoid_fast(cc[3*j + 1]), vG);
            vB = fmaf(w, sigmoid_fast(cc[3*j + 2]), vB);
            q *= o;
        }

        // warp inclusive product scan of q
        float p = q;
        #pragma unroll
        for (int dd = 1; dd < 32; dd <<= 1) {
            const float s = __shfl_up_sync(FULL_MASK, p, dd);
            if (lane >= dd) p *= s;
        }
        float excl = __shfl_up_sync(FULL_MASK, p, 1);
        if (lane == 0) excl = 1.0f;
        const float tot = __shfl_sync(FULL_MASK, p, 31);

        const float t0 = carry * excl;          // transmittance entering lane
        accR = fmaf(t0, vR, accR);
        accG = fmaf(t0, vG, accG);
        accB = fmaf(t0, vB, accB);
        carry *= tot;
    }

    // warp reduction of the color accumulators
    #pragma unroll
    for (int dd = 16; dd >= 1; dd >>= 1) {
        accR += __shfl_xor_sync(FULL_MASK, accR, dd);
        accG += __shfl_xor_sync(FULL_MASK, accG, dd);
        accB += __shfl_xor_sync(FULL_MASK, accB, dd);
    }

    if (lane == 0) {
        out[3 * warp + 0] = accR + carry;       // white background leftover
        out[3 * warp + 1] = accG + carry;
        out[3 * warp + 2] = accB + carry;
    }
}

extern "C" void kernel_launch(void* const* d_in, const int* in_sizes, int n_in,
                              void* d_out, int out_size)
{
    const float* density = (const float*)d_in[0];
    const float* rgb_raw = (const float*)d_in[1];
    const float* shift   = (const float*)d_in[2];
    const int*   ray_id  = (const int*)d_in[3];
    float*       out     = (float*)d_out;

    const int M = in_sizes[0];
    int N = out_size / 3;
    if (N > NMAX) N = NMAX;

    const int t1 = (M + 3) / 4;
    boundary_kernel<<<(t1 + 255) / 256, 256>>>(ray_id, M, N);

    const int blocks = (N + WPB - 1) / WPB;
    render_kernel<<<blocks, WPB * 32>>>(density, rgb_raw, shift, out, M, N);
}

// round 16
// speedup vs baseline: 1.1959x; 1.1959x over previous
#include <cuda_runtime.h>
#include <cuda_bf16.h>

#define FULL_MASK 0xFFFFFFFFu
#define WPB 4          // warps per block (render)
#define NMAX 65536

// Segment start offsets: g_start[r] = first sample of ray r, g_start[N] = M.
__device__ int g_start[NMAX + 1];

__device__ __forceinline__ float tanh_fast(float x) {
    float y;
    asm("tanh.approx.f32 %0, %1;" : "=f"(y) : "f"(x));
    return y;
}
// sigmoid(x) = 0.5*tanh(0.5x) + 0.5  (single MUFU)
__device__ __forceinline__ float sigmoid_fast(float x) {
    return fmaf(tanh_fast(0.5f * x), 0.5f, 0.5f);
}

// ---------------------------------------------------------------------------
// Kernel 1: boundary detection over the sorted ray_id array (int4 per thread).
// Writes g_start[r] for every boundary (covers empty rays); the tail thread
// fills g_start[last+1 .. N] = M.
// ---------------------------------------------------------------------------
__global__ void __launch_bounds__(256)
boundary_kernel(const int* __restrict__ ray_id, int M, int N)
{
    const int t = blockIdx.x * blockDim.x + threadIdx.x;
    const int i = t * 4;
    if (i >= M) return;

    if (i + 4 <= M) {
        const int4 v = *(const int4*)(ray_id + i);
        const int a = (i == 0) ? -1 : __ldg(ray_id + i - 1);
        if (a   != v.x) for (int r = a   + 1; r <= v.x; r++) g_start[r] = i;
        if (v.x != v.y) for (int r = v.x + 1; r <= v.y; r++) g_start[r] = i + 1;
        if (v.y != v.z) for (int r = v.y + 1; r <= v.z; r++) g_start[r] = i + 2;
        if (v.z != v.w) for (int r = v.z + 1; r <= v.w; r++) g_start[r] = i + 3;
        if (i + 4 == M)
            for (int r = v.w + 1; r <= N; r++) g_start[r] = M;
    } else {
        int a = (i == 0) ? -1 : __ldg(ray_id + i - 1);
        for (int j = i; j < M; j++) {
            int b = __ldg(ray_id + j);
            if (a != b) for (int r = a + 1; r <= b; r++) g_start[r] = j;
            a = b;
        }
        for (int r = a + 1; r <= N; r++) g_start[r] = M;
    }
}

// ---------------------------------------------------------------------------
// Kernel 2: one warp per ray. Each iteration processes TWO 128-sample chunks.
// Within each chunk the layout is the round-13 interleaved K=4 (lane L owns
// [chunk + 4L, +4)), so every float4 load instruction covers a contiguous
// 512B across the warp (clean L1 wavefronts). All 8 loads of both chunks are
// issued up front (MLP=8). Each chunk folds to a composite (q, vR, vG, vB);
// the two warp product-scans are INDEPENDENT and interleaved, overlapping
// their shuffle latencies, then composed sequentially through `carry`.
// A fully-invalid second chunk degenerates to the identity (q=1, v=0).
//
// Math (interval = 0.5):
//   t  = density*log2(e) + shift*log2(e)      (invalid sample -> t = -200)
//   ex = 2^t,  om = rsqrt(1+ex) = exp(-0.5*softplus(x)),  alpha = 1 - om
//   alphainv_last = final carry.
// ---------------------------------------------------------------------------
__global__ void __launch_bounds__(WPB * 32)
render_kernel(const float* __restrict__ density,
              const float* __restrict__ rgb_raw,
              const float* __restrict__ shift,
              float*       __restrict__ out,
              int M, int N)
{
    const int warp = blockIdx.x * WPB + (threadIdx.x >> 5);
    if (warp >= N) return;
    const int lane = threadIdx.x & 31;

    const float L2E = 1.4426950408889634f;
    const float shl = __ldg(shift) * L2E;

    const int start = g_start[warp];
    const int end   = g_start[warp + 1];
    const int a0    = start & ~3;               // 4-aligned loop base
    const unsigned len = (unsigned)(end - start);
    const int bmax  = M - 4;                    // highest legal float4 base

    float carry = 1.0f;
    float accR = 0.f, accG = 0.f, accB = 0.f;

    for (int itb = a0; itb < end; itb += 256) {
        const int b1  = itb + 4 * lane;         // chunk-1 lane base
        const int b2  = b1 + 128;               // chunk-2 lane base
        const int cb1 = min(b1, bmax);          // clamped (in-bounds) bases
        const int cb2 = min(b2, bmax);

        // ---- issue ALL loads of both chunks up front (MLP = 8) ----
        const float4 dA = __ldcs((const float4*)(density + cb1));
        const float4 dB = __ldcs((const float4*)(density + cb2));
        const float4* rpA = (const float4*)(rgb_raw + 3 * cb1);
        const float4* rpB = (const float4*)(rgb_raw + 3 * cb2);
        const float4 rA0 = __ldcs(rpA + 0);
        const float4 rA1 = __ldcs(rpA + 1);
        const float4 rA2 = __ldcs(rpA + 2);
        const float4 rB0 = __ldcs(rpB + 0);
        const float4 rB1 = __ldcs(rpB + 1);
        const float4 rB2 = __ldcs(rpB + 2);

        // ---- fold chunk 1 -> (q1, v1) ----
        float q1 = 1.0f, v1R = 0.f, v1G = 0.f, v1B = 0.f;
        {
            const float dv[4]  = { dA.x, dA.y, dA.z, dA.w };
            const float cc[12] = { rA0.x, rA0.y, rA0.z, rA0.w, rA1.x, rA1.y,
                                   rA1.z, rA1.w, rA2.x, rA2.y, rA2.z, rA2.w };
            #pragma unroll
            for (int j = 0; j < 4; ++j) {
                const bool valid = (unsigned)(b1 + j - start) < len;
                float t = fmaf(dv[j], L2E, shl);
                t = valid ? t : -200.0f;
                const float ex = exp2f(t);
                const float o  = rsqrtf(1.0f + ex);
                const float w  = (1.0f - o) * q1;
                v1R = fmaf(w, sigmoid_fast(cc[3*j + 0]), v1R);
                v1G = fmaf(w, sigmoid_fast(cc[3*j + 1]), v1G);
                v1B = fmaf(w, sigmoid_fast(cc[3*j + 2]), v1B);
                q1 *= o;
            }
        }
        // ---- fold chunk 2 -> (q2, v2) (identity if fully invalid) ----
        float q2 = 1.0f, v2R = 0.f, v2G = 0.f, v2B = 0.f;
        {
            const float dv[4]  = { dB.x, dB.y, dB.z, dB.w };
            const float cc[12] = { rB0.x, rB0.y, rB0.z, rB0.w, rB1.x, rB1.y,
                                   rB1.z, rB1.w, rB2.x, rB2.y, rB2.z, rB2.w };
            #pragma unroll
            for (int j = 0; j < 4; ++j) {
                const bool valid = (unsigned)(b2 + j - start) < len;
                float t = fmaf(dv[j], L2E, shl);
                t = valid ? t : -200.0f;
                const float ex = exp2f(t);
                const float o  = rsqrtf(1.0f + ex);
                const float w  = (1.0f - o) * q2;
                v2R = fmaf(w, sigmoid_fast(cc[3*j + 0]), v2R);
                v2G = fmaf(w, sigmoid_fast(cc[3*j + 1]), v2G);
                v2B = fmaf(w, sigmoid_fast(cc[3*j + 2]), v2B);
                q2 *= o;
            }
        }

        // ---- two INDEPENDENT warp product scans, interleaved for ILP ----
        float p1 = q1, p2 = q2;
        #pragma unroll
        for (int dd = 1; dd < 32; dd <<= 1) {
            const float s1 = __shfl_up_sync(FULL_MASK, p1, dd);
            const float s2 = __shfl_up_sync(FULL_MASK, p2, dd);
            if (lane >= dd) { p1 *= s1; p2 *= s2; }
        }
        float e1 = __shfl_up_sync(FULL_MASK, p1, 1);
        float e2 = __shfl_up_sync(FULL_MASK, p2, 1);
        if (lane == 0) { e1 = 1.0f; e2 = 1.0f; }
        const float tot1 = __shfl_sync(FULL_MASK, p1, 31);
        const float tot2 = __shfl_sync(FULL_MASK, p2, 31);

        // ---- sequential composition through carry ----
        const float t1 = carry * e1;
        accR = fmaf(t1, v1R, accR);
        accG = fmaf(t1, v1G, accG);
        accB = fmaf(t1, v1B, accB);
        carry *= tot1;

        const float t2 = carry * e2;
        accR = fmaf(t2, v2R, accR);
        accG = fmaf(t2, v2G, accG);
        accB = fmaf(t2, v2B, accB);
        carry *= tot2;
    }

    // warp reduction of the color accumulators
    #pragma unroll
    for (int dd = 16; dd >= 1; dd >>= 1) {
        accR += __shfl_xor_sync(FULL_MASK, accR, dd);
        accG += __shfl_xor_sync(FULL_MASK, accG, dd);
        accB += __shfl_xor_sync(FULL_MASK, accB, dd);
    }

    if (lane == 0) {
        out[3 * warp + 0] = accR + carry;       // white background leftover
        out[3 * warp + 1] = accG + carry;
        out[3 * warp + 2] = accB + carry;
    }
}

extern "C" void kernel_launch(void* const* d_in, const int* in_sizes, int n_in,
                              void* d_out, int out_size)
{
    const float* density = (const float*)d_in[0];
    const float* rgb_raw = (const float*)d_in[1];
    const float* shift   = (const float*)d_in[2];
    const int*   ray_id  = (const int*)d_in[3];
    float*       out     = (float*)d_out;

    const int M = in_sizes[0];
    int N = out_size / 3;
    if (N > NMAX) N = NMAX;

    const int t1 = (M + 3) / 4;
    boundary_kernel<<<(t1 + 255) / 256, 256>>>(ray_id, M, N);

    const int blocks = (N + WPB - 1) / WPB;
    render_kernel<<<blocks, WPB * 32>>>(density, rgb_raw, shift, out, M, N);
}